// round 15
// baseline (speedup 1.0000x reference)
#include <cuda_runtime.h>
#include <cuda_fp16.h>
#include <cstdint>

#define NN 256
#define CH 20

// fp16 E/bias matrix, 2-pass split layout: 144 rows x 64 cols (row n permuted).
__device__ __align__(16) __half gEH[144 * 64];
// fp32 E/bias copy for the border path: [w=p*9+k][28] (0..24 E, 25 bias).
__device__ __align__(16) float gEF[144 * 28];

__device__ __forceinline__ void mma16816(float& d0, float& d1, float& d2, float& d3,
                                         uint32_t a0, uint32_t a1, uint32_t a2, uint32_t a3,
                                         uint32_t b0, uint32_t b1) {
    asm volatile(
        "mma.sync.aligned.m16n8k16.row.col.f32.f16.f16.f32 "
        "{%0,%1,%2,%3}, {%4,%5,%6,%7}, {%8,%9}, {%0,%1,%2,%3};"
        : "+f"(d0), "+f"(d1), "+f"(d2), "+f"(d3)
        : "r"(a0), "r"(a1), "r"(a2), "r"(a3), "r"(b0), "r"(b1));
}

__device__ __forceinline__ void ldmx4(uint32_t& r0, uint32_t& r1, uint32_t& r2,
                                      uint32_t& r3, uint32_t a) {
    asm volatile("ldmatrix.sync.aligned.m8n8.x4.shared.b16 {%0,%1,%2,%3}, [%4];"
                 : "=r"(r0), "=r"(r1), "=r"(r2), "=r"(r3) : "r"(a));
}

// ---------------------------------------------------------------------------
// Kernel 1: compose W1/W2 -> 5x5 E + bias; emit fp16 split planes + fp32 copy.
// ---------------------------------------------------------------------------
__global__ void k_precompute(const float* __restrict__ W1, const float* __restrict__ b1,
                             const float* __restrict__ W2, const float* __restrict__ b2) {
    int w = blockIdx.x * 4 + (threadIdx.x >> 5);
    int lane = threadIdx.x & 31;
    if (w >= 144) return;
    int p = w / 9, k9 = w % 9;

    float e[25];
#pragma unroll
    for (int i = 0; i < 25; i++) e[i] = 0.f;
    float bacc = 0.f;

    if (lane < CH) {
        int c = lane;
        float w1[9];
        const float* w1p = W1 + (p * CH + c) * 9;
#pragma unroll
        for (int a = 0; a < 9; a++) w1[a] = __ldg(w1p + a);
        const float* w2p = W2 + ((p * 9 + k9) * CH + c) * 9;
        float s2 = 0.f;
#pragma unroll
        for (int bq = 0; bq < 9; bq++) {
            float w2v = __ldg(w2p + bq);
            s2 += w2v;
            int by = bq / 3, bx = bq % 3;
#pragma unroll
            for (int a = 0; a < 9; a++) {
                int ay = a / 3, ax = a % 3;
                e[(ay + by) * 5 + (ax + bx)] += w1[a] * w2v;
            }
        }
        bacc = s2 * __ldg(b1 + p * CH + c);
    }
#pragma unroll
    for (int o = 16; o > 0; o >>= 1) {
#pragma unroll
        for (int i = 0; i < 25; i++) e[i] += __shfl_xor_sync(0xFFFFFFFFu, e[i], o);
        bacc += __shfl_xor_sync(0xFFFFFFFFu, bacc, o);
    }

    if (lane == 0) {
        int i = p >> 2, j = p & 3;
        int n = (j * 9 + k9) * 4 + i;
        __half* d = gEH + n * 64;
        float B = __ldg(b2 + w) + bacc;
        __half bh = __float2half(B);
        __half bl = __float2half(B - __half2float(bh));
#pragma unroll
        for (int q = 0; q < 64; q++) {
            __half v;
            if (q < 26)      v = (q == 25) ? bh : __float2half(e[q]);
            else if (q < 52) v = (q == 51) ? bl : __float2half(e[q - 26]);
            else             v = __ushort_as_half(0);
            d[q] = v;
        }
        float* df = gEF + w * 28;
#pragma unroll
        for (int q = 0; q < 25; q++) df[q] = e[q];
        df[25] = B; df[26] = 0.f; df[27] = 0.f;
    }
}

__device__ __forceinline__ constexpr int OFFJK2(int jk) {
    return (jk / 9) * 324 + ((jk % 9) / 3) * 18 + ((jk % 9) % 3);
}

// ---------------------------------------------------------------------------
// Border path (device fn): final ring values computed independently:
//   exact = composed(E fp32) - sum_{q oob} W2[k,c,q]*htilde_c(q).
// One thread = (ring pixel, out-channel i); loops j. Direct store, no atomics.
// All weights via __ldg (uniform addresses -> L1 broadcast). Low reg pressure.
// ---------------------------------------------------------------------------
__device__ void border_block(const float* __restrict__ img, const float* __restrict__ x,
                             const float* __restrict__ W1, const float* __restrict__ b1,
                             const float* __restrict__ W2, float* __restrict__ y) {
    const int ich = blockIdx.x;          // 0..3 (callers guarantee blockIdx.x < 4)
    const int t = threadIdx.x;
    int idx = blockIdx.y * 256 + t;
    if (idx >= 4080) return;
    int b = idx / 1020;
    int r = idx % 1020;
    int n, m;
    if (r < 256)       { n = 0;   m = r; }
    else if (r < 512)  { n = 255; m = r - 256; }
    else if (r < 766)  { n = r - 511; m = 0;   }
    else               { n = r - 765; m = 255; }

    const float* imgb = img + b * NN * NN;
    float ipat[25];
#pragma unroll
    for (int u = 0; u < 5; u++)
#pragma unroll
        for (int v = 0; v < 5; v++) {
            int gn = n + u - 2, gm = m + v - 2;
            ipat[u * 5 + v] = ((unsigned)gn < NN && (unsigned)gm < NN)
                              ? __ldg(imgb + gn * NN + gm) : 0.f;
        }

    float out = 0.f;
#pragma unroll 1
    for (int j = 0; j < 4; j++) {
        const int p = ich * 4 + j;

        // composed K from fp32 E
        float K[9];
#pragma unroll
        for (int k = 0; k < 9; k++) {
            const float* e = gEF + (p * 9 + k) * 28;
            float s = __ldg(e + 25);
#pragma unroll
            for (int q = 0; q < 25; q++) s = fmaf(__ldg(e + q), ipat[q], s);
            K[k] = s;
        }

        // subtract oob corrections
#pragma unroll 1
        for (int qq = 0; qq < 9; qq++) {
            const int qy = qq / 3, qx = qq % 3;
            const int py = n + qy - 1, px = m + qx - 1;
            if (((unsigned)py >= NN) | ((unsigned)px >= NN)) {
#pragma unroll 1
                for (int c = 0; c < CH; c++) {
                    const float* w1p = W1 + (p * CH + c) * 9;
                    float h = __ldg(b1 + p * CH + c);
#pragma unroll
                    for (int a = 0; a < 9; a++) {
                        int ay = a / 3, ax = a % 3;
                        h = fmaf(__ldg(w1p + a), ipat[(qy + ay) * 5 + qx + ax], h);
                    }
                    const float* w2p = W2 + p * 9 * CH * 9 + c * 9 + qq;
#pragma unroll
                    for (int k = 0; k < 9; k++)
                        K[k] = fmaf(-__ldg(w2p + k * CH * 9), h, K[k]);
                }
            }
        }

        // contract with x patch
        const float* xb = x + (b * 4 + j) * NN * NN;
#pragma unroll
        for (int k = 0; k < 9; k++) {
            int di = k / 3, dj = k % 3;
            int gn = n + di - 1, gm = m + dj - 1;
            float xv = ((unsigned)gn < NN && (unsigned)gm < NN)
                       ? __ldg(xb + gn * NN + gm) : 0.f;
            out = fmaf(K[k], xv, out);
        }
    }
    y[((b * 4 + ich) * NN + n) * NN + m] = out;
}

// ---------------------------------------------------------------------------
// Fused kernel: bz==0 (and bx<4) -> border blocks, scheduled first (wave 1);
// bz 1..4 -> HMMA main (K'=64, fp16 split-2), ring stores predicated off.
// ---------------------------------------------------------------------------
__global__ void __launch_bounds__(256, 4) k_fused(const float* __restrict__ img,
                                                  const float* __restrict__ x,
                                                  const float* __restrict__ W1,
                                                  const float* __restrict__ b1,
                                                  const float* __restrict__ W2,
                                                  float* __restrict__ y) {
    if (blockIdx.z == 0) {
        if (blockIdx.x < 4) border_block(img, x, W1, b1, W2, y);
        return;
    }

    __shared__ uint32_t sImgP[400];                   // 20x20 packed (hi|lo<<16) fp16
    __shared__ float sX[1296];                        // 4 x 18 x 18
    __shared__ __align__(16) uint32_t sB[144 * 36];   // row stride 36 words (144 B)

    const int t = threadIdx.x;
    const int w = t >> 5, lane = t & 31;
    const int g = lane >> 2, tg = lane & 3;
    const int b = blockIdx.z - 1, TR = blockIdx.y * 16, TC = blockIdx.x * 16;

    const float* imgb = img + b * NN * NN;
    for (int i = t; i < 400; i += 256) {
        int rr = i / 20, cc = i % 20;
        int gn = TR + rr - 2, gm = TC + cc - 2;
        float f = 0.f;
        if ((unsigned)gn < NN && (unsigned)gm < NN) f = __ldg(imgb + gn * NN + gm);
        __half h = __float2half(f);
        __half l = __float2half(f - __half2float(h));
        sImgP[i] = (uint32_t)__half_as_ushort(h)
                 | ((uint32_t)__half_as_ushort(l) << 16);
    }
#pragma unroll
    for (int j = 0; j < 4; j++) {
        const float* xb = x + (b * 4 + j) * NN * NN;
        for (int i = t; i < 324; i += 256) {
            int rr = i / 18, cc = i % 18;
            int gn = TR + rr - 1, gm = TC + cc - 1;
            float v = 0.f;
            if ((unsigned)gn < NN && (unsigned)gm < NN) v = __ldg(xb + gn * NN + gm);
            sX[j * 324 + i] = v;
        }
    }
    {   // stage B (144 x 64 fp16 = 1152 uint4), row stride 36 words
        const uint4* src = reinterpret_cast<const uint4*>(gEH);
        for (int i = t; i < 1152; i += 256) {
            int n = i >> 3, q = i & 7;
            uint4 v = __ldg(src + i);
            *reinterpret_cast<uint4*>(&sB[n * 36 + q * 4]) = v;
        }
    }
    __syncthreads();

    // --- build A fragments for two pixel rows (r0, r0+1): 4 K-steps ---
    const int r0 = 2 * w;
    const int pc0 = g, pc1 = g + 8;
    uint32_t af0[4][4], af1[4][4];
#pragma unroll
    for (int ks = 0; ks < 4; ks++) {
#pragma unroll
        for (int hf = 0; hf < 2; hf++) {
            const int c = ks * 16 + 2 * tg + 8 * hf;
            uint32_t v[2][4];
#pragma unroll
            for (int dc = 0; dc < 2; dc++) {
                const int cc = c + dc;
                int k, sh;
                if (cc < 26)      { k = cc;      sh = 0;  }
                else if (cc < 52) { k = cc - 26; sh = 16; }
                else              { k = 0;       sh = 0;  }
                const bool zero = (cc >= 52);
                const bool bias = (k == 25);
                const int o = (k / 5) * 20 + (k % 5);
                const int base = r0 * 20 + o;
                uint32_t u0, u1, u2, u3;
                if (zero)      { u0 = u1 = u2 = u3 = 0u; }
                else if (bias) { u0 = u1 = u2 = u3 = 0x3C00u; }
                else {
                    u0 = (sImgP[base + pc0] >> sh) & 0xFFFFu;
                    u1 = (sImgP[base + pc1] >> sh) & 0xFFFFu;
                    u2 = (sImgP[base + 20 + pc0] >> sh) & 0xFFFFu;
                    u3 = (sImgP[base + 20 + pc1] >> sh) & 0xFFFFu;
                }
                v[dc][0] = u0; v[dc][1] = u1; v[dc][2] = u2; v[dc][3] = u3;
            }
            af0[ks][hf * 2 + 0] = v[0][0] | (v[1][0] << 16);
            af0[ks][hf * 2 + 1] = v[0][1] | (v[1][1] << 16);
            af1[ks][hf * 2 + 0] = v[0][2] | (v[1][2] << 16);
            af1[ks][hf * 2 + 1] = v[0][3] | (v[1][3] << 16);
        }
    }

    float sa00 = 0.f, sb00 = 0.f, sa01 = 0.f, sb01 = 0.f;
    float sa10 = 0.f, sb10 = 0.f, sa11 = 0.f, sb11 = 0.f;
    const int th = tg >> 1;
    const int xb0 = r0 * 18, xb1 = (r0 + 1) * 18;

    const uint32_t sbB = (uint32_t)__cvta_generic_to_shared(sB);
    const uint32_t mbase = sbB + (uint32_t)(lane & 7) * 144u + (uint32_t)(lane >> 3) * 16u;

#pragma unroll
    for (int ni = 0; ni < 18; ni++) {
        const uint32_t ad = mbase + (uint32_t)ni * 1152u;
        uint32_t c0, c1, c2, c3, c4, c5, c6, c7;
        ldmx4(c0, c1, c2, c3, ad);
        ldmx4(c4, c5, c6, c7, ad + 64);

        float d00 = 0.f, d01 = 0.f, d02 = 0.f, d03 = 0.f;
        float d10 = 0.f, d11 = 0.f, d12 = 0.f, d13 = 0.f;
        mma16816(d00, d01, d02, d03, af0[0][0], af0[0][1], af0[0][2], af0[0][3], c0, c1);
        mma16816(d10, d11, d12, d13, af1[0][0], af1[0][1], af1[0][2], af1[0][3], c0, c1);
        mma16816(d00, d01, d02, d03, af0[1][0], af0[1][1], af0[1][2], af0[1][3], c2, c3);
        mma16816(d10, d11, d12, d13, af1[1][0], af1[1][1], af1[1][2], af1[1][3], c2, c3);
        mma16816(d00, d01, d02, d03, af0[2][0], af0[2][1], af0[2][2], af0[2][3], c4, c5);
        mma16816(d10, d11, d12, d13, af1[2][0], af1[2][1], af1[2][2], af1[2][3], c4, c5);
        mma16816(d00, d01, d02, d03, af0[3][0], af0[3][1], af0[3][2], af0[3][3], c6, c7);
        mma16816(d10, d11, d12, d13, af1[3][0], af1[3][1], af1[3][2], af1[3][3], c6, c7);

        const int offA = OFFJK2(2 * ni);
        const int offB = OFFJK2(2 * ni + 1);
        const int off = th ? offB : offA;
        float x00 = sX[off + xb0 + pc0];
        float x01 = sX[off + xb0 + pc1];
        float x10 = sX[off + xb1 + pc0];
        float x11 = sX[off + xb1 + pc1];
        sa00 = fmaf(d00, x00, sa00);
        sb00 = fmaf(d01, x00, sb00);
        sa01 = fmaf(d02, x01, sa01);
        sb01 = fmaf(d03, x01, sb01);
        sa10 = fmaf(d10, x10, sa10);
        sb10 = fmaf(d11, x10, sb10);
        sa11 = fmaf(d12, x11, sa11);
        sb11 = fmaf(d13, x11, sb11);
    }

    sa00 += __shfl_xor_sync(0xFFFFFFFFu, sa00, 2);
    sb00 += __shfl_xor_sync(0xFFFFFFFFu, sb00, 2);
    sa01 += __shfl_xor_sync(0xFFFFFFFFu, sa01, 2);
    sb01 += __shfl_xor_sync(0xFFFFFFFFu, sb01, 2);
    sa10 += __shfl_xor_sync(0xFFFFFFFFu, sa10, 2);
    sb10 += __shfl_xor_sync(0xFFFFFFFFu, sb10, 2);
    sa11 += __shfl_xor_sync(0xFFFFFFFFu, sa11, 2);
    sb11 += __shfl_xor_sync(0xFFFFFFFFu, sb11, 2);

    if (tg < 2) {
        const int ch0 = tg * 2;
        const int gc0 = TC + pc0, gc1 = TC + pc1;
        const int gr0 = TR + r0;
        const bool mc0 = (gc0 == 0) | (gc0 == NN - 1);
        const bool mc1 = (gc1 == 0) | (gc1 == NN - 1);
        const bool ra = (gr0 == 0);
        const bool rb = (gr0 + 1 == NN - 1);
        float* y0 = y + ((b * 4 + ch0) * NN + gr0) * NN;
        float* y1 = y + ((b * 4 + ch0 + 1) * NN + gr0) * NN;
        if (!(ra | mc0)) { y0[gc0] = sa00; y1[gc0] = sb00; }
        if (!(ra | mc1)) { y0[gc1] = sa01; y1[gc1] = sb01; }
        if (!(rb | mc0)) { y0[NN + gc0] = sa10; y1[NN + gc0] = sb10; }
        if (!(rb | mc1)) { y0[NN + gc1] = sa11; y1[NN + gc1] = sb11; }
    }
}

// ---------------------------------------------------------------------------
extern "C" void kernel_launch(void* const* d_in, const int* in_sizes, int n_in,
                              void* d_out, int out_size) {
    const float* image = (const float*)d_in[0];
    const float* x     = (const float*)d_in[1];
    const float* W1    = (const float*)d_in[2];
    const float* b1    = (const float*)d_in[3];
    const float* W2    = (const float*)d_in[4];
    const float* b2    = (const float*)d_in[5];
    float* y = (float*)d_out;

    k_precompute<<<36, 128>>>(W1, b1, W2, b2);           // launch 1
    dim3 gf(16, 16, 5);                                  // bz0 border, bz1..4 main
    k_fused<<<gf, 256>>>(image, x, W1, b1, W2, y);       // launch 2
}

// round 16
// speedup vs baseline: 2.4443x; 2.4443x over previous
#include <cuda_runtime.h>
#include <cuda_fp16.h>
#include <cstdint>

#define NN 256
#define CH 20

// fp16 E/bias matrix, 2-pass split layout: 144 rows x 64 cols (row n permuted).
__device__ __align__(16) __half gEH[144 * 64];
// fp32 E/bias copy for the border path: [w=p*9+k][28] (0..24 E, 25 bias).
__device__ __align__(16) float gEF[144 * 28];
// Correction kernels: gG[w=p*9+k][q][a] (3x3 per oob position q), gBq[w][q].
__device__ __align__(16) float gG[144 * 81];
__device__ __align__(16) float gBq[144 * 9];

__device__ __forceinline__ void mma16816(float& d0, float& d1, float& d2, float& d3,
                                         uint32_t a0, uint32_t a1, uint32_t a2, uint32_t a3,
                                         uint32_t b0, uint32_t b1) {
    asm volatile(
        "mma.sync.aligned.m16n8k16.row.col.f32.f16.f16.f32 "
        "{%0,%1,%2,%3}, {%4,%5,%6,%7}, {%8,%9}, {%0,%1,%2,%3};"
        : "+f"(d0), "+f"(d1), "+f"(d2), "+f"(d3)
        : "r"(a0), "r"(a1), "r"(a2), "r"(a3), "r"(b0), "r"(b1));
}

__device__ __forceinline__ void ldmx4(uint32_t& r0, uint32_t& r1, uint32_t& r2,
                                      uint32_t& r3, uint32_t a) {
    asm volatile("ldmatrix.sync.aligned.m8n8.x4.shared.b16 {%0,%1,%2,%3}, [%4];"
                 : "=r"(r0), "=r"(r1), "=r"(r2), "=r"(r3) : "r"(a));
}

// ---------------------------------------------------------------------------
// Kernel 1: compose W1/W2 -> 5x5 E + bias (fp16 split planes + fp32 copy),
// plus per-q correction kernels G[q] = sum_c W2[:,c,q] (x) W1[c,:], Bq.
// ---------------------------------------------------------------------------
__global__ void k_precompute(const float* __restrict__ W1, const float* __restrict__ b1,
                             const float* __restrict__ W2, const float* __restrict__ b2) {
    int w = blockIdx.x * 4 + (threadIdx.x >> 5);
    int lane = threadIdx.x & 31;
    if (w >= 144) return;
    int p = w / 9, k9 = w % 9;

    float e[25];
#pragma unroll
    for (int i = 0; i < 25; i++) e[i] = 0.f;
    float bacc = 0.f;

    float w1[9], w2r[9], b1c = 0.f;
#pragma unroll
    for (int a = 0; a < 9; a++) { w1[a] = 0.f; w2r[a] = 0.f; }

    if (lane < CH) {
        int c = lane;
        const float* w1p = W1 + (p * CH + c) * 9;
#pragma unroll
        for (int a = 0; a < 9; a++) w1[a] = __ldg(w1p + a);
        const float* w2p = W2 + ((p * 9 + k9) * CH + c) * 9;
        b1c = __ldg(b1 + p * CH + c);
        float s2 = 0.f;
#pragma unroll
        for (int bq = 0; bq < 9; bq++) {
            float w2v = __ldg(w2p + bq);
            w2r[bq] = w2v;
            s2 += w2v;
            int by = bq / 3, bx = bq % 3;
#pragma unroll
            for (int a = 0; a < 9; a++) {
                int ay = a / 3, ax = a % 3;
                e[(ay + by) * 5 + (ax + bx)] += w1[a] * w2v;
            }
        }
        bacc = s2 * b1c;
    }
#pragma unroll
    for (int o = 16; o > 0; o >>= 1) {
#pragma unroll
        for (int i = 0; i < 25; i++) e[i] += __shfl_xor_sync(0xFFFFFFFFu, e[i], o);
        bacc += __shfl_xor_sync(0xFFFFFFFFu, bacc, o);
    }

    if (lane == 0) {
        int i = p >> 2, j = p & 3;
        int n = (j * 9 + k9) * 4 + i;
        __half* d = gEH + n * 64;
        float B = __ldg(b2 + w) + bacc;
        __half bh = __float2half(B);
        __half bl = __float2half(B - __half2float(bh));
#pragma unroll
        for (int q = 0; q < 64; q++) {
            __half v;
            if (q < 26)      v = (q == 25) ? bh : __float2half(e[q]);
            else if (q < 52) v = (q == 51) ? bl : __float2half(e[q - 26]);
            else             v = __ushort_as_half(0);
            d[q] = v;
        }
        float* df = gEF + w * 28;
#pragma unroll
        for (int q = 0; q < 25; q++) df[q] = e[q];
        df[25] = B; df[26] = 0.f; df[27] = 0.f;
    }

    // Correction kernels, chunked per q to keep live set small.
#pragma unroll 1
    for (int q = 0; q < 9; q++) {
        float gq[9];
#pragma unroll
        for (int a = 0; a < 9; a++) gq[a] = w1[a] * w2r[q];
        float bqv = b1c * w2r[q];
#pragma unroll
        for (int o = 16; o > 0; o >>= 1) {
#pragma unroll
            for (int a = 0; a < 9; a++) gq[a] += __shfl_xor_sync(0xFFFFFFFFu, gq[a], o);
            bqv += __shfl_xor_sync(0xFFFFFFFFu, bqv, o);
        }
        if (lane == 0) {
            float* gg = gG + w * 81 + q * 9;
#pragma unroll
            for (int a = 0; a < 9; a++) gg[a] = gq[a];
            gBq[w * 9 + q] = bqv;
        }
    }
}

__device__ __forceinline__ constexpr int OFFJK2(int jk) {
    return (jk / 9) * 324 + ((jk % 9) / 3) * 18 + ((jk % 9) % 3);
}

// ---------------------------------------------------------------------------
// Border path: final ring values directly:
//   exact = composed(E fp32) - sum_{q oob} (Bq + G[q] * img_patch(q)).
// One thread = (ring pixel, out-channel); loops j. No atomics, no smem.
// ---------------------------------------------------------------------------
__device__ void border_block(const float* __restrict__ img, const float* __restrict__ x,
                             float* __restrict__ y) {
    const int ich = blockIdx.x;          // 0..3
    const int t = threadIdx.x;
    int idx = blockIdx.y * 256 + t;
    if (idx >= 4080) return;
    int b = idx / 1020;
    int r = idx % 1020;
    int n, m;
    if (r < 256)       { n = 0;   m = r; }
    else if (r < 512)  { n = 255; m = r - 256; }
    else if (r < 766)  { n = r - 511; m = 0;   }
    else               { n = r - 765; m = 255; }

    const float* imgb = img + b * NN * NN;
    float ipat[25];
#pragma unroll
    for (int u = 0; u < 5; u++)
#pragma unroll
        for (int v = 0; v < 5; v++) {
            int gn = n + u - 2, gm = m + v - 2;
            ipat[u * 5 + v] = ((unsigned)gn < NN && (unsigned)gm < NN)
                              ? __ldg(imgb + gn * NN + gm) : 0.f;
        }

    float out = 0.f;
#pragma unroll 1
    for (int j = 0; j < 4; j++) {
        const int p = ich * 4 + j;

        float K[9];
#pragma unroll
        for (int k = 0; k < 9; k++) {
            const float* e = gEF + (p * 9 + k) * 28;
            float s = __ldg(e + 25);
#pragma unroll
            for (int q = 0; q < 25; q++) s = fmaf(__ldg(e + q), ipat[q], s);
            K[k] = s;
        }

#pragma unroll
        for (int qq = 0; qq < 9; qq++) {
            const int qy = qq / 3, qx = qq % 3;
            const int py = n + qy - 1, px = m + qx - 1;
            if (((unsigned)py >= NN) | ((unsigned)px >= NN)) {
#pragma unroll
                for (int k = 0; k < 9; k++) {
                    const int wk = p * 9 + k;
                    float s = __ldg(gBq + wk * 9 + qq);
                    const float* g = gG + wk * 81 + qq * 9;
#pragma unroll
                    for (int a = 0; a < 9; a++)
                        s = fmaf(__ldg(g + a), ipat[(qy + a / 3) * 5 + qx + a % 3], s);
                    K[k] -= s;
                }
            }
        }

        const float* xb = x + (b * 4 + j) * NN * NN;
#pragma unroll
        for (int k = 0; k < 9; k++) {
            int di = k / 3, dj = k % 3;
            int gn = n + di - 1, gm = m + dj - 1;
            float xv = ((unsigned)gn < NN && (unsigned)gm < NN)
                       ? __ldg(xb + gn * NN + gm) : 0.f;
            out = fmaf(K[k], xv, out);
        }
    }
    y[((b * 4 + ich) * NN + n) * NN + m] = out;
}

// ---------------------------------------------------------------------------
// Fused kernel: bz==0 (bx<4) -> border blocks (wave 1, overlap with main);
// bz 1..4 -> HMMA main (K'=64, fp16 split-2), ring stores predicated off.
// ---------------------------------------------------------------------------
__global__ void __launch_bounds__(256, 4) k_fused(const float* __restrict__ img,
                                                  const float* __restrict__ x,
                                                  float* __restrict__ y) {
    if (blockIdx.z == 0) {
        if (blockIdx.x < 4) border_block(img, x, y);
        return;
    }

    __shared__ uint32_t sImgP[400];                   // 20x20 packed (hi|lo<<16) fp16
    __shared__ float sX[1296];                        // 4 x 18 x 18
    __shared__ __align__(16) uint32_t sB[144 * 36];   // row stride 36 words (144 B)

    const int t = threadIdx.x;
    const int w = t >> 5, lane = t & 31;
    const int g = lane >> 2, tg = lane & 3;
    const int b = blockIdx.z - 1, TR = blockIdx.y * 16, TC = blockIdx.x * 16;

    const float* imgb = img + b * NN * NN;
    for (int i = t; i < 400; i += 256) {
        int rr = i / 20, cc = i % 20;
        int gn = TR + rr - 2, gm = TC + cc - 2;
        float f = 0.f;
        if ((unsigned)gn < NN && (unsigned)gm < NN) f = __ldg(imgb + gn * NN + gm);
        __half h = __float2half(f);
        __half l = __float2half(f - __half2float(h));
        sImgP[i] = (uint32_t)__half_as_ushort(h)
                 | ((uint32_t)__half_as_ushort(l) << 16);
    }
#pragma unroll
    for (int j = 0; j < 4; j++) {
        const float* xb = x + (b * 4 + j) * NN * NN;
        for (int i = t; i < 324; i += 256) {
            int rr = i / 18, cc = i % 18;
            int gn = TR + rr - 1, gm = TC + cc - 1;
            float v = 0.f;
            if ((unsigned)gn < NN && (unsigned)gm < NN) v = __ldg(xb + gn * NN + gm);
            sX[j * 324 + i] = v;
        }
    }
    {   // stage B (144 x 64 fp16 = 1152 uint4), row stride 36 words
        const uint4* src = reinterpret_cast<const uint4*>(gEH);
        for (int i = t; i < 1152; i += 256) {
            int n = i >> 3, q = i & 7;
            uint4 v = __ldg(src + i);
            *reinterpret_cast<uint4*>(&sB[n * 36 + q * 4]) = v;
        }
    }
    __syncthreads();

    // --- build A fragments for two pixel rows (r0, r0+1): 4 K-steps ---
    const int r0 = 2 * w;
    const int pc0 = g, pc1 = g + 8;
    uint32_t af0[4][4], af1[4][4];
#pragma unroll
    for (int ks = 0; ks < 4; ks++) {
#pragma unroll
        for (int hf = 0; hf < 2; hf++) {
            const int c = ks * 16 + 2 * tg + 8 * hf;
            uint32_t v[2][4];
#pragma unroll
            for (int dc = 0; dc < 2; dc++) {
                const int cc = c + dc;
                int k, sh;
                if (cc < 26)      { k = cc;      sh = 0;  }
                else if (cc < 52) { k = cc - 26; sh = 16; }
                else              { k = 0;       sh = 0;  }
                const bool zero = (cc >= 52);
                const bool bias = (k == 25);
                const int o = (k / 5) * 20 + (k % 5);
                const int base = r0 * 20 + o;
                uint32_t u0, u1, u2, u3;
                if (zero)      { u0 = u1 = u2 = u3 = 0u; }
                else if (bias) { u0 = u1 = u2 = u3 = 0x3C00u; }
                else {
                    u0 = (sImgP[base + pc0] >> sh) & 0xFFFFu;
                    u1 = (sImgP[base + pc1] >> sh) & 0xFFFFu;
                    u2 = (sImgP[base + 20 + pc0] >> sh) & 0xFFFFu;
                    u3 = (sImgP[base + 20 + pc1] >> sh) & 0xFFFFu;
                }
                v[dc][0] = u0; v[dc][1] = u1; v[dc][2] = u2; v[dc][3] = u3;
            }
            af0[ks][hf * 2 + 0] = v[0][0] | (v[1][0] << 16);
            af0[ks][hf * 2 + 1] = v[0][1] | (v[1][1] << 16);
            af1[ks][hf * 2 + 0] = v[0][2] | (v[1][2] << 16);
            af1[ks][hf * 2 + 1] = v[0][3] | (v[1][3] << 16);
        }
    }

    float sa00 = 0.f, sb00 = 0.f, sa01 = 0.f, sb01 = 0.f;
    float sa10 = 0.f, sb10 = 0.f, sa11 = 0.f, sb11 = 0.f;
    const int th = tg >> 1;
    const int xb0 = r0 * 18, xb1 = (r0 + 1) * 18;

    const uint32_t sbB = (uint32_t)__cvta_generic_to_shared(sB);
    const uint32_t mbase = sbB + (uint32_t)(lane & 7) * 144u + (uint32_t)(lane >> 3) * 16u;

#pragma unroll
    for (int ni = 0; ni < 18; ni++) {
        const uint32_t ad = mbase + (uint32_t)ni * 1152u;
        uint32_t c0, c1, c2, c3, c4, c5, c6, c7;
        ldmx4(c0, c1, c2, c3, ad);
        ldmx4(c4, c5, c6, c7, ad + 64);

        float d00 = 0.f, d01 = 0.f, d02 = 0.f, d03 = 0.f;
        float d10 = 0.f, d11 = 0.f, d12 = 0.f, d13 = 0.f;
        mma16816(d00, d01, d02, d03, af0[0][0], af0[0][1], af0[0][2], af0[0][3], c0, c1);
        mma16816(d10, d11, d12, d13, af1[0][0], af1[0][1], af1[0][2], af1[0][3], c0, c1);
        mma16816(d00, d01, d02, d03, af0[1][0], af0[1][1], af0[1][2], af0[1][3], c2, c3);
        mma16816(d10, d11, d12, d13, af1[1][0], af1[1][1], af1[1][2], af1[1][3], c2, c3);
        mma16816(d00, d01, d02, d03, af0[2][0], af0[2][1], af0[2][2], af0[2][3], c4, c5);
        mma16816(d10, d11, d12, d13, af1[2][0], af1[2][1], af1[2][2], af1[2][3], c4, c5);
        mma16816(d00, d01, d02, d03, af0[3][0], af0[3][1], af0[3][2], af0[3][3], c6, c7);
        mma16816(d10, d11, d12, d13, af1[3][0], af1[3][1], af1[3][2], af1[3][3], c6, c7);

        const int offA = OFFJK2(2 * ni);
        const int offB = OFFJK2(2 * ni + 1);
        const int off = th ? offB : offA;
        float x00 = sX[off + xb0 + pc0];
        float x01 = sX[off + xb0 + pc1];
        float x10 = sX[off + xb1 + pc0];
        float x11 = sX[off + xb1 + pc1];
        sa00 = fmaf(d00, x00, sa00);
        sb00 = fmaf(d01, x00, sb00);
        sa01 = fmaf(d02, x01, sa01);
        sb01 = fmaf(d03, x01, sb01);
        sa10 = fmaf(d10, x10, sa10);
        sb10 = fmaf(d11, x10, sb10);
        sa11 = fmaf(d12, x11, sa11);
        sb11 = fmaf(d13, x11, sb11);
    }

    sa00 += __shfl_xor_sync(0xFFFFFFFFu, sa00, 2);
    sb00 += __shfl_xor_sync(0xFFFFFFFFu, sb00, 2);
    sa01 += __shfl_xor_sync(0xFFFFFFFFu, sa01, 2);
    sb01 += __shfl_xor_sync(0xFFFFFFFFu, sb01, 2);
    sa10 += __shfl_xor_sync(0xFFFFFFFFu, sa10, 2);
    sb10 += __shfl_xor_sync(0xFFFFFFFFu, sb10, 2);
    sa11 += __shfl_xor_sync(0xFFFFFFFFu, sa11, 2);
    sb11 += __shfl_xor_sync(0xFFFFFFFFu, sb11, 2);

    if (tg < 2) {
        const int ch0 = tg * 2;
        const int gc0 = TC + pc0, gc1 = TC + pc1;
        const int gr0 = TR + r0;
        const bool mc0 = (gc0 == 0) | (gc0 == NN - 1);
        const bool mc1 = (gc1 == 0) | (gc1 == NN - 1);
        const bool ra = (gr0 == 0);
        const bool rb = (gr0 + 1 == NN - 1);
        float* y0 = y + ((b * 4 + ch0) * NN + gr0) * NN;
        float* y1 = y + ((b * 4 + ch0 + 1) * NN + gr0) * NN;
        if (!(ra | mc0)) { y0[gc0] = sa00; y1[gc0] = sb00; }
        if (!(ra | mc1)) { y0[gc1] = sa01; y1[gc1] = sb01; }
        if (!(rb | mc0)) { y0[NN + gc0] = sa10; y1[NN + gc0] = sb10; }
        if (!(rb | mc1)) { y0[NN + gc1] = sa11; y1[NN + gc1] = sb11; }
    }
}

// ---------------------------------------------------------------------------
extern "C" void kernel_launch(void* const* d_in, const int* in_sizes, int n_in,
                              void* d_out, int out_size) {
    const float* image = (const float*)d_in[0];
    const float* x     = (const float*)d_in[1];
    const float* W1    = (const float*)d_in[2];
    const float* b1    = (const float*)d_in[3];
    const float* W2    = (const float*)d_in[4];
    const float* b2    = (const float*)d_in[5];
    float* y = (float*)d_out;

    k_precompute<<<36, 128>>>(W1, b1, W2, b2);           // launch 1
    dim3 gf(16, 16, 5);                                  // bz0 border, bz1..4 main
    k_fused<<<gf, 256>>>(image, x, y);                   // launch 2
}

// round 17
// speedup vs baseline: 3.6608x; 1.4977x over previous
#include <cuda_runtime.h>
#include <cuda_fp16.h>
#include <cstdint>

#define NN 256
#define CH 20

// fp16 E/bias matrix, 2-pass split layout: 144 rows x 64 cols (row n permuted).
__device__ __align__(16) __half gEH[144 * 64];
// fp32 E/bias copy for the border path: [w=p*9+k][28] (0..24 E, 25 bias).
__device__ __align__(16) float gEF[144 * 28];
// Correction kernels: gG[w=p*9+k][q][a] (3x3 per oob position q), gBq[w][q].
__device__ __align__(16) float gG[144 * 81];
__device__ __align__(16) float gBq[144 * 9];

__device__ __forceinline__ void mma16816(float& d0, float& d1, float& d2, float& d3,
                                         uint32_t a0, uint32_t a1, uint32_t a2, uint32_t a3,
                                         uint32_t b0, uint32_t b1) {
    asm volatile(
        "mma.sync.aligned.m16n8k16.row.col.f32.f16.f16.f32 "
        "{%0,%1,%2,%3}, {%4,%5,%6,%7}, {%8,%9}, {%0,%1,%2,%3};"
        : "+f"(d0), "+f"(d1), "+f"(d2), "+f"(d3)
        : "r"(a0), "r"(a1), "r"(a2), "r"(a3), "r"(b0), "r"(b1));
}

__device__ __forceinline__ void ldmx4(uint32_t& r0, uint32_t& r1, uint32_t& r2,
                                      uint32_t& r3, uint32_t a) {
    asm volatile("ldmatrix.sync.aligned.m8n8.x4.shared.b16 {%0,%1,%2,%3}, [%4];"
                 : "=r"(r0), "=r"(r1), "=r"(r2), "=r"(r3) : "r"(a));
}

// ---------------------------------------------------------------------------
// Kernel 1: compose W1/W2 -> 5x5 E + bias (fp16 split planes + fp32 copy),
// plus per-q correction kernels G[q] = sum_c W2[:,c,q] (x) W1[c,:], Bq.
// ---------------------------------------------------------------------------
__global__ void k_precompute(const float* __restrict__ W1, const float* __restrict__ b1,
                             const float* __restrict__ W2, const float* __restrict__ b2) {
    int w = blockIdx.x * 4 + (threadIdx.x >> 5);
    int lane = threadIdx.x & 31;
    if (w >= 144) return;
    int p = w / 9, k9 = w % 9;

    float e[25];
#pragma unroll
    for (int i = 0; i < 25; i++) e[i] = 0.f;
    float bacc = 0.f;

    float w1[9], w2r[9], b1c = 0.f;
#pragma unroll
    for (int a = 0; a < 9; a++) { w1[a] = 0.f; w2r[a] = 0.f; }

    if (lane < CH) {
        int c = lane;
        const float* w1p = W1 + (p * CH + c) * 9;
#pragma unroll
        for (int a = 0; a < 9; a++) w1[a] = __ldg(w1p + a);
        const float* w2p = W2 + ((p * 9 + k9) * CH + c) * 9;
        b1c = __ldg(b1 + p * CH + c);
        float s2 = 0.f;
#pragma unroll
        for (int bq = 0; bq < 9; bq++) {
            float w2v = __ldg(w2p + bq);
            w2r[bq] = w2v;
            s2 += w2v;
            int by = bq / 3, bx = bq % 3;
#pragma unroll
            for (int a = 0; a < 9; a++) {
                int ay = a / 3, ax = a % 3;
                e[(ay + by) * 5 + (ax + bx)] += w1[a] * w2v;
            }
        }
        bacc = s2 * b1c;
    }
#pragma unroll
    for (int o = 16; o > 0; o >>= 1) {
#pragma unroll
        for (int i = 0; i < 25; i++) e[i] += __shfl_xor_sync(0xFFFFFFFFu, e[i], o);
        bacc += __shfl_xor_sync(0xFFFFFFFFu, bacc, o);
    }

    if (lane == 0) {
        int i = p >> 2, j = p & 3;
        int n = (j * 9 + k9) * 4 + i;
        __half* d = gEH + n * 64;
        float B = __ldg(b2 + w) + bacc;
        __half bh = __float2half(B);
        __half bl = __float2half(B - __half2float(bh));
#pragma unroll
        for (int q = 0; q < 64; q++) {
            __half v;
            if (q < 26)      v = (q == 25) ? bh : __float2half(e[q]);
            else if (q < 52) v = (q == 51) ? bl : __float2half(e[q - 26]);
            else             v = __ushort_as_half(0);
            d[q] = v;
        }
        float* df = gEF + w * 28;
#pragma unroll
        for (int q = 0; q < 25; q++) df[q] = e[q];
        df[25] = B; df[26] = 0.f; df[27] = 0.f;
    }

    // Correction kernels, chunked per q to keep live set small.
#pragma unroll 1
    for (int q = 0; q < 9; q++) {
        float gq[9];
#pragma unroll
        for (int a = 0; a < 9; a++) gq[a] = w1[a] * w2r[q];
        float bqv = b1c * w2r[q];
#pragma unroll
        for (int o = 16; o > 0; o >>= 1) {
#pragma unroll
            for (int a = 0; a < 9; a++) gq[a] += __shfl_xor_sync(0xFFFFFFFFu, gq[a], o);
            bqv += __shfl_xor_sync(0xFFFFFFFFu, bqv, o);
        }
        if (lane == 0) {
            float* gg = gG + w * 81 + q * 9;
#pragma unroll
            for (int a = 0; a < 9; a++) gg[a] = gq[a];
            gBq[w * 9 + q] = bqv;
        }
    }
}

__device__ __forceinline__ constexpr int OFFJK2(int jk) {
    return (jk / 9) * 324 + ((jk % 9) / 3) * 18 + ((jk % 9) % 3);
}

// ---------------------------------------------------------------------------
// Border path: thread = (ring pixel, out-channel i, in-channel j).
// 4 consecutive lanes share a pixel (j = t&3); j-partials merged by shfl.
//   exact = composed(E fp32) - sum_{q oob} (Bq + G[q] * img_patch(q)).
// 256 blocks (full bz=0 slice). No atomics, no smem.
// ---------------------------------------------------------------------------
__device__ void border_block(const float* __restrict__ img, const float* __restrict__ x,
                             float* __restrict__ y) {
    const int bb = blockIdx.y * 16 + blockIdx.x;   // 0..255
    const int ich = bb & 3;
    const int chunk = bb >> 2;                     // 0..63
    const int t = threadIdx.x;
    const int j = t & 3;

    int idx = chunk * 64 + (t >> 2);               // 0..4095
    const bool active = (idx < 4080);
    if (!active) idx = 0;
    int b = idx / 1020;
    int r = idx % 1020;
    int n, m;
    if (r < 256)       { n = 0;   m = r; }
    else if (r < 512)  { n = 255; m = r - 256; }
    else if (r < 766)  { n = r - 511; m = 0;   }
    else               { n = r - 765; m = 255; }

    const float* imgb = img + b * NN * NN;
    float ipat[25];
#pragma unroll
    for (int u = 0; u < 5; u++)
#pragma unroll
        for (int v = 0; v < 5; v++) {
            int gn = n + u - 2, gm = m + v - 2;
            ipat[u * 5 + v] = ((unsigned)gn < NN && (unsigned)gm < NN)
                              ? __ldg(imgb + gn * NN + gm) : 0.f;
        }

    const int p = ich * 4 + j;

    // composed K from fp32 E
    float K[9];
#pragma unroll
    for (int k = 0; k < 9; k++) {
        const float* e = gEF + (p * 9 + k) * 28;
        float s = __ldg(e + 25);
#pragma unroll
        for (int q = 0; q < 25; q++) s = fmaf(__ldg(e + q), ipat[q], s);
        K[k] = s;
    }

    // subtract oob corrections via precomposed G / Bq
#pragma unroll
    for (int qq = 0; qq < 9; qq++) {
        const int qy = qq / 3, qx = qq % 3;
        const int py = n + qy - 1, px = m + qx - 1;
        if (((unsigned)py >= NN) | ((unsigned)px >= NN)) {
#pragma unroll
            for (int k = 0; k < 9; k++) {
                const int wk = p * 9 + k;
                float s = __ldg(gBq + wk * 9 + qq);
                const float* gk = gG + wk * 81 + qq * 9;
#pragma unroll
                for (int a = 0; a < 9; a++)
                    s = fmaf(__ldg(gk + a), ipat[(qy + a / 3) * 5 + qx + a % 3], s);
                K[k] -= s;
            }
        }
    }

    // contract with x patch for this j
    const float* xb = x + (b * 4 + j) * NN * NN;
    float partial = 0.f;
#pragma unroll
    for (int k = 0; k < 9; k++) {
        int di = k / 3, dj = k % 3;
        int gn = n + di - 1, gm = m + dj - 1;
        float xv = ((unsigned)gn < NN && (unsigned)gm < NN)
                   ? __ldg(xb + gn * NN + gm) : 0.f;
        partial = fmaf(K[k], xv, partial);
    }

    // reduce the 4 j-partials (lanes 4q..4q+3 share a pixel)
    partial += __shfl_xor_sync(0xFFFFFFFFu, partial, 1);
    partial += __shfl_xor_sync(0xFFFFFFFFu, partial, 2);

    if (active && j == 0)
        y[((b * 4 + ich) * NN + n) * NN + m] = partial;
}

// ---------------------------------------------------------------------------
// Fused kernel: bz==0 -> border blocks (wave 1, overlap with main);
// bz 1..4 -> HMMA main (K'=64, fp16 split-2), ring stores predicated off.
// ---------------------------------------------------------------------------
__global__ void __launch_bounds__(256, 4) k_fused(const float* __restrict__ img,
                                                  const float* __restrict__ x,
                                                  float* __restrict__ y) {
    if (blockIdx.z == 0) {
        border_block(img, x, y);
        return;
    }

    __shared__ uint32_t sImgP[400];                   // 20x20 packed (hi|lo<<16) fp16
    __shared__ float sX[1296];                        // 4 x 18 x 18
    __shared__ __align__(16) uint32_t sB[144 * 36];   // row stride 36 words (144 B)

    const int t = threadIdx.x;
    const int w = t >> 5, lane = t & 31;
    const int g = lane >> 2, tg = lane & 3;
    const int b = blockIdx.z - 1, TR = blockIdx.y * 16, TC = blockIdx.x * 16;

    const float* imgb = img + b * NN * NN;
    for (int i = t; i < 400; i += 256) {
        int rr = i / 20, cc = i % 20;
        int gn = TR + rr - 2, gm = TC + cc - 2;
        float f = 0.f;
        if ((unsigned)gn < NN && (unsigned)gm < NN) f = __ldg(imgb + gn * NN + gm);
        __half h = __float2half(f);
        __half l = __float2half(f - __half2float(h));
        sImgP[i] = (uint32_t)__half_as_ushort(h)
                 | ((uint32_t)__half_as_ushort(l) << 16);
    }
#pragma unroll
    for (int j = 0; j < 4; j++) {
        const float* xb = x + (b * 4 + j) * NN * NN;
        for (int i = t; i < 324; i += 256) {
            int rr = i / 18, cc = i % 18;
            int gn = TR + rr - 1, gm = TC + cc - 1;
            float v = 0.f;
            if ((unsigned)gn < NN && (unsigned)gm < NN) v = __ldg(xb + gn * NN + gm);
            sX[j * 324 + i] = v;
        }
    }
    {   // stage B (144 x 64 fp16 = 1152 uint4), row stride 36 words
        const uint4* src = reinterpret_cast<const uint4*>(gEH);
        for (int i = t; i < 1152; i += 256) {
            int n = i >> 3, q = i & 7;
            uint4 v = __ldg(src + i);
            *reinterpret_cast<uint4*>(&sB[n * 36 + q * 4]) = v;
        }
    }
    __syncthreads();

    // --- build A fragments for two pixel rows (r0, r0+1): 4 K-steps ---
    const int r0 = 2 * w;
    const int pc0 = g, pc1 = g + 8;
    uint32_t af0[4][4], af1[4][4];
#pragma unroll
    for (int ks = 0; ks < 4; ks++) {
#pragma unroll
        for (int hf = 0; hf < 2; hf++) {
            const int c = ks * 16 + 2 * tg + 8 * hf;
            uint32_t v[2][4];
#pragma unroll
            for (int dc = 0; dc < 2; dc++) {
                const int cc = c + dc;
                int k, sh;
                if (cc < 26)      { k = cc;      sh = 0;  }
                else if (cc < 52) { k = cc - 26; sh = 16; }
                else              { k = 0;       sh = 0;  }
                const bool zero = (cc >= 52);
                const bool bias = (k == 25);
                const int o = (k / 5) * 20 + (k % 5);
                const int base = r0 * 20 + o;
                uint32_t u0, u1, u2, u3;
                if (zero)      { u0 = u1 = u2 = u3 = 0u; }
                else if (bias) { u0 = u1 = u2 = u3 = 0x3C00u; }
                else {
                    u0 = (sImgP[base + pc0] >> sh) & 0xFFFFu;
                    u1 = (sImgP[base + pc1] >> sh) & 0xFFFFu;
                    u2 = (sImgP[base + 20 + pc0] >> sh) & 0xFFFFu;
                    u3 = (sImgP[base + 20 + pc1] >> sh) & 0xFFFFu;
                }
                v[dc][0] = u0; v[dc][1] = u1; v[dc][2] = u2; v[dc][3] = u3;
            }
            af0[ks][hf * 2 + 0] = v[0][0] | (v[1][0] << 16);
            af0[ks][hf * 2 + 1] = v[0][1] | (v[1][1] << 16);
            af1[ks][hf * 2 + 0] = v[0][2] | (v[1][2] << 16);
            af1[ks][hf * 2 + 1] = v[0][3] | (v[1][3] << 16);
        }
    }

    float sa00 = 0.f, sb00 = 0.f, sa01 = 0.f, sb01 = 0.f;
    float sa10 = 0.f, sb10 = 0.f, sa11 = 0.f, sb11 = 0.f;
    const int th = tg >> 1;
    const int xb0 = r0 * 18, xb1 = (r0 + 1) * 18;

    const uint32_t sbB = (uint32_t)__cvta_generic_to_shared(sB);
    const uint32_t mbase = sbB + (uint32_t)(lane & 7) * 144u + (uint32_t)(lane >> 3) * 16u;

#pragma unroll
    for (int ni = 0; ni < 18; ni++) {
        const uint32_t ad = mbase + (uint32_t)ni * 1152u;
        uint32_t c0, c1, c2, c3, c4, c5, c6, c7;
        ldmx4(c0, c1, c2, c3, ad);
        ldmx4(c4, c5, c6, c7, ad + 64);

        float d00 = 0.f, d01 = 0.f, d02 = 0.f, d03 = 0.f;
        float d10 = 0.f, d11 = 0.f, d12 = 0.f, d13 = 0.f;
        mma16816(d00, d01, d02, d03, af0[0][0], af0[0][1], af0[0][2], af0[0][3], c0, c1);
        mma16816(d10, d11, d12, d13, af1[0][0], af1[0][1], af1[0][2], af1[0][3], c0, c1);
        mma16816(d00, d01, d02, d03, af0[1][0], af0[1][1], af0[1][2], af0[1][3], c2, c3);
        mma16816(d10, d11, d12, d13, af1[1][0], af1[1][1], af1[1][2], af1[1][3], c2, c3);
        mma16816(d00, d01, d02, d03, af0[2][0], af0[2][1], af0[2][2], af0[2][3], c4, c5);
        mma16816(d10, d11, d12, d13, af1[2][0], af1[2][1], af1[2][2], af1[2][3], c4, c5);
        mma16816(d00, d01, d02, d03, af0[3][0], af0[3][1], af0[3][2], af0[3][3], c6, c7);
        mma16816(d10, d11, d12, d13, af1[3][0], af1[3][1], af1[3][2], af1[3][3], c6, c7);

        const int offA = OFFJK2(2 * ni);
        const int offB = OFFJK2(2 * ni + 1);
        const int off = th ? offB : offA;
        float x00 = sX[off + xb0 + pc0];
        float x01 = sX[off + xb0 + pc1];
        float x10 = sX[off + xb1 + pc0];
        float x11 = sX[off + xb1 + pc1];
        sa00 = fmaf(d00, x00, sa00);
        sb00 = fmaf(d01, x00, sb00);
        sa01 = fmaf(d02, x01, sa01);
        sb01 = fmaf(d03, x01, sb01);
        sa10 = fmaf(d10, x10, sa10);
        sb10 = fmaf(d11, x10, sb10);
        sa11 = fmaf(d12, x11, sa11);
        sb11 = fmaf(d13, x11, sb11);
    }

    sa00 += __shfl_xor_sync(0xFFFFFFFFu, sa00, 2);
    sb00 += __shfl_xor_sync(0xFFFFFFFFu, sb00, 2);
    sa01 += __shfl_xor_sync(0xFFFFFFFFu, sa01, 2);
    sb01 += __shfl_xor_sync(0xFFFFFFFFu, sb01, 2);
    sa10 += __shfl_xor_sync(0xFFFFFFFFu, sa10, 2);
    sb10 += __shfl_xor_sync(0xFFFFFFFFu, sb10, 2);
    sa11 += __shfl_xor_sync(0xFFFFFFFFu, sa11, 2);
    sb11 += __shfl_xor_sync(0xFFFFFFFFu, sb11, 2);

    if (tg < 2) {
        const int ch0 = tg * 2;
        const int gc0 = TC + pc0, gc1 = TC + pc1;
        const int gr0 = TR + r0;
        const bool mc0 = (gc0 == 0) | (gc0 == NN - 1);
        const bool mc1 = (gc1 == 0) | (gc1 == NN - 1);
        const bool ra = (gr0 == 0);
        const bool rb = (gr0 + 1 == NN - 1);
        float* y0 = y + ((b * 4 + ch0) * NN + gr0) * NN;
        float* y1 = y + ((b * 4 + ch0 + 1) * NN + gr0) * NN;
        if (!(ra | mc0)) { y0[gc0] = sa00; y1[gc0] = sb00; }
        if (!(ra | mc1)) { y0[gc1] = sa01; y1[gc1] = sb01; }
        if (!(rb | mc0)) { y0[NN + gc0] = sa10; y1[NN + gc0] = sb10; }
        if (!(rb | mc1)) { y0[NN + gc1] = sa11; y1[NN + gc1] = sb11; }
    }
}

// ---------------------------------------------------------------------------
extern "C" void kernel_launch(void* const* d_in, const int* in_sizes, int n_in,
                              void* d_out, int out_size) {
    const float* image = (const float*)d_in[0];
    const float* x     = (const float*)d_in[1];
    const float* W1    = (const float*)d_in[2];
    const float* b1    = (const float*)d_in[3];
    const float* W2    = (const float*)d_in[4];
    const float* b2    = (const float*)d_in[5];
    float* y = (float*)d_out;

    k_precompute<<<36, 128>>>(W1, b1, W2, b2);           // launch 1
    dim3 gf(16, 16, 5);                                  // bz0 border, bz1..4 main
    k_fused<<<gf, 256>>>(image, x, y);                   // launch 2
}